// round 7
// baseline (speedup 1.0000x reference)
#include <cuda_runtime.h>
#include <cuda_fp16.h>

#define N_NODES 200000
#define N_EDGES 600000
#define EE_TOT  800000
#define NGRAPH  20000
#define DIM     128
#define NEG_SLOPE 0.2f
#define LN_EPS 1e-5f

// ---------------- device scratch: total ~63.3 MB ----------------
__device__ int    g_idx64;
__device__ __align__(16) __half g_hbuf[(long long)N_NODES*DIM]; // 51.2 MB, layer-1 activations
__device__ __align__(16) float  g_asrc[N_NODES*4];              // 3.2 MB
__device__ __align__(16) float  g_adst[N_NODES*4];              // 3.2 MB
__device__ int    g_col[EE_TOT];                                // 3.2 MB
__device__ int    g_rowptr[N_NODES+1];
__device__ int    g_deg[N_NODES];
__device__ int    g_fill[N_NODES];
__device__ int    g_bsum[512];
__device__ float  g_gcnt[NGRAPH];
__device__ float  g_p1[4*DIM], g_q1[4*DIM];   // projected att vectors, layer 1
__device__ float  g_p2[DIM],   g_q2[DIM];     // layer 2

__device__ __forceinline__ int load_idx(const void* p, long long i) {
    if (g_idx64) return (int)((const long long*)p)[i];
    return ((const int*)p)[i];
}
__device__ __forceinline__ float lrelu(float a) { return a > 0.0f ? a : NEG_SLOPE * a; }

// ---------------- dtype sniff ----------------
__global__ void k_detect(const void* ei) {
    const int* p = (const int*)ei;
    int orr = 0;
    for (int i = 1; i < 2000; i += 2) orr |= p[i];
    g_idx64 = (orr == 0) ? 1 : 0;
}

// ---------------- init / histogram / CSR ----------------
__global__ void k_init() {
    int i = blockIdx.x * blockDim.x + threadIdx.x;
    if (i < N_NODES) { g_deg[i] = 1; g_fill[i] = 0; }   // self loop
    if (i < NGRAPH)  g_gcnt[i] = 0.0f;
}
__global__ void k_zero_out(float* out) {
    int i = blockIdx.x * blockDim.x + threadIdx.x;
    if (i < NGRAPH * DIM) out[i] = 0.0f;
}
__global__ void k_hist(const void* batch) {
    int i = blockIdx.x * blockDim.x + threadIdx.x;
    if (i < N_NODES) atomicAdd(&g_gcnt[load_idx(batch, i)], 1.0f);
}
__global__ void k_deg(const void* ei) {
    int e = blockIdx.x * blockDim.x + threadIdx.x;
    if (e < N_EDGES) atomicAdd(&g_deg[load_idx(ei, (long long)N_EDGES + e)], 1);
}
__global__ void k_scan1() {
    __shared__ int sh[512];
    int gid = blockIdx.x * 512 + threadIdx.x;
    int v = (gid < N_NODES) ? g_deg[gid] : 0;
    sh[threadIdx.x] = v;
    __syncthreads();
    for (int off = 1; off < 512; off <<= 1) {
        int t = (threadIdx.x >= off) ? sh[threadIdx.x - off] : 0;
        __syncthreads();
        sh[threadIdx.x] += t;
        __syncthreads();
    }
    if (gid < N_NODES) g_rowptr[gid] = sh[threadIdx.x] - v;
    if (threadIdx.x == 511) g_bsum[blockIdx.x] = sh[511];
}
__global__ void k_scan2(int nblocks) {
    if (threadIdx.x == 0 && blockIdx.x == 0) {
        int run = 0;
        for (int i = 0; i < nblocks; i++) { int t = g_bsum[i]; g_bsum[i] = run; run += t; }
    }
}
__global__ void k_scan3() {
    int gid = blockIdx.x * 512 + threadIdx.x;
    if (gid < N_NODES) g_rowptr[gid] += g_bsum[blockIdx.x];
    if (gid == 0) g_rowptr[N_NODES] = EE_TOT;
}
__global__ void k_scatter(const void* ei) {
    int e = blockIdx.x * blockDim.x + threadIdx.x;
    if (e >= EE_TOT) return;
    int s, d;
    if (e < N_EDGES) {
        s = load_idx(ei, e);
        d = load_idx(ei, (long long)N_EDGES + e);
    } else {
        s = d = e - N_EDGES;
    }
    int pos = g_rowptr[d] + atomicAdd(&g_fill[d], 1);
    g_col[pos] = s;
}

// ---------------- projected attention vectors ----------------
// p1[h][c] = sum_j W1[c][h*32+j]*att_s1[h][j]   (a_src1[n,h] = x[n]·p1[h])
__global__ void k_proj1(const float* __restrict__ W1,
                        const float* __restrict__ as1,
                        const float* __restrict__ ad1) {
    int c = threadIdx.x;
#pragma unroll
    for (int hd = 0; hd < 4; hd++) {
        float sp = 0.0f, sq = 0.0f;
#pragma unroll
        for (int j = 0; j < 32; j++) {
            float wv = W1[c * 128 + hd * 32 + j];
            sp += wv * as1[hd * 32 + j];
            sq += wv * ad1[hd * 32 + j];
        }
        g_p1[hd * 128 + c] = sp;
        g_q1[hd * 128 + c] = sq;
    }
}
__global__ void k_proj2(const float* __restrict__ W2,
                        const float* __restrict__ as2,
                        const float* __restrict__ ad2) {
    int c = threadIdx.x;
    float sp = 0.0f, sq = 0.0f;
    for (int j = 0; j < 128; j++) {
        float wv = W2[c * 128 + j];
        sp += wv * as2[j];
        sq += wv * ad2[j];
    }
    g_p2[c] = sp;
    g_q2[c] = sq;
}

// ---------------- a_src/a_dst per node ----------------
__global__ void k_dots_x(const float* __restrict__ x) {
    int n    = (blockIdx.x * blockDim.x + threadIdx.x) >> 5;
    int lane = threadIdx.x & 31;
    if (n >= N_NODES) return;
    float4 xv = *(const float4*)&x[(long long)n * 128 + lane * 4];
    float s[4], d[4];
#pragma unroll
    for (int hd = 0; hd < 4; hd++) {
        float4 pv = *(const float4*)&g_p1[hd * 128 + lane * 4];
        float4 qv = *(const float4*)&g_q1[hd * 128 + lane * 4];
        s[hd] = xv.x * pv.x + xv.y * pv.y + xv.z * pv.z + xv.w * pv.w;
        d[hd] = xv.x * qv.x + xv.y * qv.y + xv.z * qv.z + xv.w * qv.w;
    }
#pragma unroll
    for (int hd = 0; hd < 4; hd++)
#pragma unroll
        for (int o = 16; o; o >>= 1) {
            s[hd] += __shfl_xor_sync(0xFFFFFFFFu, s[hd], o);
            d[hd] += __shfl_xor_sync(0xFFFFFFFFu, d[hd], o);
        }
    if (lane == 0) {
        *(float4*)&g_asrc[n * 4] = make_float4(s[0], s[1], s[2], s[3]);
        *(float4*)&g_adst[n * 4] = make_float4(d[0], d[1], d[2], d[3]);
    }
}
__global__ void k_dots_h() {
    int n    = (blockIdx.x * blockDim.x + threadIdx.x) >> 5;
    int lane = threadIdx.x & 31;
    if (n >= N_NODES) return;
    const __half2* row2 = (const __half2*)&g_hbuf[(long long)n * 128];
    float2 va = __half22float2(row2[lane]);
    float2 vb = __half22float2(row2[32 + lane]);
    int cA = 2 * lane, cB = 64 + 2 * lane;
    float s = va.x * g_p2[cA] + va.y * g_p2[cA + 1] + vb.x * g_p2[cB] + vb.y * g_p2[cB + 1];
    float d = va.x * g_q2[cA] + va.y * g_q2[cA + 1] + vb.x * g_q2[cB] + vb.y * g_q2[cB + 1];
#pragma unroll
    for (int o = 16; o; o >>= 1) {
        s += __shfl_xor_sync(0xFFFFFFFFu, s, o);
        d += __shfl_xor_sync(0xFFFFFFFFu, d, o);
    }
    if (lane == 0) { g_asrc[n] = s; g_adst[n] = d; }
}

// ---------------- layer 1 fused: aggregate(x) + per-head GEMM + bias + relu --
// 256 threads, 32 dst rows/block. smem: Ush 32x512 half (32KB) + Wsh 128x32 f32 (16KB)
__global__ __launch_bounds__(256) void k_fused1(const float* __restrict__ x,
                                                const float* __restrict__ W1,
                                                const float* __restrict__ b1) {
    __shared__ __half Ush[32 * 512];
    __shared__ float  Wsh[128 * 32];
    int t = threadIdx.x;
    int w = t >> 5, lane = t & 31;
    long long rowBase = (long long)blockIdx.x * 32;

    // Phase A: per-head softmax aggregation in input space
    for (int rr = 0; rr < 4; rr++) {
        int row = w * 4 + rr;
        long long n = rowBase + row;
        int beg = g_rowptr[n], end = g_rowptr[n + 1];
        float4 ad = *(const float4*)&g_adst[n * 4];
        float m0 = -1e30f, m1 = -1e30f, m2 = -1e30f, m3 = -1e30f;
        for (int e = beg; e < end; e++) {
            int s = g_col[e];
            float4 as = *(const float4*)&g_asrc[s * 4];
            m0 = fmaxf(m0, lrelu(as.x + ad.x));
            m1 = fmaxf(m1, lrelu(as.y + ad.y));
            m2 = fmaxf(m2, lrelu(as.z + ad.z));
            m3 = fmaxf(m3, lrelu(as.w + ad.w));
        }
        float acc[4][4];
#pragma unroll
        for (int a = 0; a < 4; a++)
#pragma unroll
            for (int b = 0; b < 4; b++) acc[a][b] = 0.0f;
        float den0 = 0, den1 = 0, den2 = 0, den3 = 0;
        for (int e = beg; e < end; e++) {
            int s = g_col[e];
            float4 as = *(const float4*)&g_asrc[s * 4];
            float w0 = __expf(lrelu(as.x + ad.x) - m0); den0 += w0;
            float w1 = __expf(lrelu(as.y + ad.y) - m1); den1 += w1;
            float w2 = __expf(lrelu(as.z + ad.z) - m2); den2 += w2;
            float w3 = __expf(lrelu(as.w + ad.w) - m3); den3 += w3;
            float4 xv = *(const float4*)&x[(long long)s * 128 + lane * 4];
            acc[0][0] += w0 * xv.x; acc[0][1] += w0 * xv.y; acc[0][2] += w0 * xv.z; acc[0][3] += w0 * xv.w;
            acc[1][0] += w1 * xv.x; acc[1][1] += w1 * xv.y; acc[1][2] += w1 * xv.z; acc[1][3] += w1 * xv.w;
            acc[2][0] += w2 * xv.x; acc[2][1] += w2 * xv.y; acc[2][2] += w2 * xv.z; acc[2][3] += w2 * xv.w;
            acc[3][0] += w3 * xv.x; acc[3][1] += w3 * xv.y; acc[3][2] += w3 * xv.z; acc[3][3] += w3 * xv.w;
        }
        float den[4] = {den0, den1, den2, den3};
#pragma unroll
        for (int hd = 0; hd < 4; hd++) {
            float inv = 1.0f / den[hd];
            __half2* dst = (__half2*)&Ush[row * 512 + hd * 128 + lane * 4];
            dst[0] = __floats2half2_rn(acc[hd][0] * inv, acc[hd][1] * inv);
            dst[1] = __floats2half2_rn(acc[hd][2] * inv, acc[hd][3] * inv);
        }
    }

    // Phase B: per-head GEMM u_hd[32,128] @ W1[:, hd*32:+32]
    int row = t >> 3;   // 0..31
    int tx8 = t & 7;    // col group of 4 within 32
    for (int hd = 0; hd < 4; hd++) {
        __syncthreads();   // Phase A done / previous head's Wsh reads done
#pragma unroll
        for (int p = 0; p < 4; p++) {
            int idx = t + p * 256;        // 0..1023
            int r   = idx >> 3;           // 0..127
            int c4  = idx & 7;
            *(float4*)&Wsh[r * 32 + c4 * 4] = *(const float4*)&W1[r * 128 + hd * 32 + c4 * 4];
        }
        __syncthreads();
        float a0 = 0, a1 = 0, a2 = 0, a3 = 0;
        const __half2* u2 = (const __half2*)&Ush[row * 512 + hd * 128];
#pragma unroll 16
        for (int k2 = 0; k2 < 64; k2++) {
            float2 av = __half22float2(u2[k2]);
            const float* w0 = &Wsh[(2 * k2) * 32 + tx8 * 4];
            const float* w1 = &Wsh[(2 * k2 + 1) * 32 + tx8 * 4];
            a0 += av.x * w0[0] + av.y * w1[0];
            a1 += av.x * w0[1] + av.y * w1[1];
            a2 += av.x * w0[2] + av.y * w1[2];
            a3 += av.x * w0[3] + av.y * w1[3];
        }
        int c = hd * 32 + tx8 * 4;
        long long n = rowBase + row;
        float v0 = a0 + b1[c];     v0 = v0 > 0 ? v0 : 0.0f;
        float v1 = a1 + b1[c + 1]; v1 = v1 > 0 ? v1 : 0.0f;
        float v2 = a2 + b1[c + 2]; v2 = v2 > 0 ? v2 : 0.0f;
        float v3 = a3 + b1[c + 3]; v3 = v3 > 0 ? v3 : 0.0f;
        __half2* dst = (__half2*)&g_hbuf[n * 128 + c];
        dst[0] = __floats2half2_rn(v0, v1);
        dst[1] = __floats2half2_rn(v2, v3);
    }
}

// ---------------- layer 2 fused: aggregate(h1) + GEMM + bias + LN + pool -----
// 512 threads, 64 dst rows/block. smem: Ash 64x128 f32 (32KB) + Wsh 32x128 f32 (16KB)
__global__ __launch_bounds__(512) void k_fused2(const float* __restrict__ W2,
                                                const float* __restrict__ b2,
                                                const float* __restrict__ gamma,
                                                const float* __restrict__ beta,
                                                const void* batch,
                                                float* __restrict__ out) {
    __shared__ float Ash[64 * 128];
    __shared__ float Wsh[32 * 128];
    int t = threadIdx.x;
    int w = t >> 5, lane = t & 31;
    long long rowBase = (long long)blockIdx.x * 64;

    // Phase A: softmax aggregation of h1 (single head)
    for (int rr = 0; rr < 4; rr++) {
        int row = w * 4 + rr;
        long long n = rowBase + row;
        int beg = g_rowptr[n], end = g_rowptr[n + 1];
        float ad = g_adst[n];
        float m = -1e30f;
        for (int e = beg; e < end; e++)
            m = fmaxf(m, lrelu(g_asrc[g_col[e]] + ad));
        float a0 = 0, a1 = 0, a2 = 0, a3 = 0, den = 0;
        for (int e = beg; e < end; e++) {
            int s = g_col[e];
            float wgt = __expf(lrelu(g_asrc[s] + ad) - m);
            den += wgt;
            const __half2* hp = (const __half2*)&g_hbuf[(long long)s * 128 + lane * 4];
            float2 p0 = __half22float2(hp[0]);
            float2 p1 = __half22float2(hp[1]);
            a0 += wgt * p0.x; a1 += wgt * p0.y; a2 += wgt * p1.x; a3 += wgt * p1.y;
        }
        float inv = 1.0f / den;
        *(float4*)&Ash[row * 128 + lane * 4] = make_float4(a0 * inv, a1 * inv, a2 * inv, a3 * inv);
    }
    __syncthreads();

    // Phase B: GEMM 64x128 @ 128x128 (4x4 register blocking)
    int tx = t & 31, ty = t >> 5;
    float acc[4][4];
#pragma unroll
    for (int i = 0; i < 4; i++)
#pragma unroll
        for (int j = 0; j < 4; j++) acc[i][j] = 0.0f;
    for (int kt = 0; kt < 128; kt += 32) {
#pragma unroll
        for (int p = 0; p < 2; p++) {
            int idx = t + p * 512;
            int kk  = idx >> 5;
            int c4  = idx & 31;
            *(float4*)&Wsh[kk * 128 + c4 * 4] = *(const float4*)&W2[(kt + kk) * 128 + c4 * 4];
        }
        __syncthreads();
#pragma unroll
        for (int k = 0; k < 32; k++) {
            float4 wv = *(const float4*)&Wsh[k * 128 + tx * 4];
#pragma unroll
            for (int i = 0; i < 4; i++) {
                float a = Ash[(ty * 4 + i) * 128 + kt + k];
                acc[i][0] += a * wv.x;
                acc[i][1] += a * wv.y;
                acc[i][2] += a * wv.z;
                acc[i][3] += a * wv.w;
            }
        }
        __syncthreads();
    }

    // epilogue: bias + layernorm (warp owns rows ty*4..+3 fully) + graph pool
    float4 b2v = *(const float4*)&b2[tx * 4];
    float4 gv  = *(const float4*)&gamma[tx * 4];
    float4 bev = *(const float4*)&beta[tx * 4];
#pragma unroll
    for (int i = 0; i < 4; i++) {
        long long n = rowBase + ty * 4 + i;
        float v0 = acc[i][0] + b2v.x;
        float v1 = acc[i][1] + b2v.y;
        float v2 = acc[i][2] + b2v.z;
        float v3 = acc[i][3] + b2v.w;
        float s = v0 + v1 + v2 + v3;
#pragma unroll
        for (int o = 16; o; o >>= 1) s += __shfl_xor_sync(0xFFFFFFFFu, s, o);
        float mu = s * (1.0f / 128.0f);
        float c0 = v0 - mu, c1 = v1 - mu, c2 = v2 - mu, c3 = v3 - mu;
        float sq = c0 * c0 + c1 * c1 + c2 * c2 + c3 * c3;
#pragma unroll
        for (int o = 16; o; o >>= 1) sq += __shfl_xor_sync(0xFFFFFFFFu, sq, o);
        float rstd = rsqrtf(sq * (1.0f / 128.0f) + LN_EPS);
        float y0 = c0 * rstd * gv.x + bev.x;
        float y1 = c1 * rstd * gv.y + bev.y;
        float y2 = c2 * rstd * gv.z + bev.z;
        float y3 = c3 * rstd * gv.w + bev.w;
        int g = load_idx(batch, n);
        float* gp = &out[(long long)g * 128 + tx * 4];
        atomicAdd(gp + 0, y0);
        atomicAdd(gp + 1, y1);
        atomicAdd(gp + 2, y2);
        atomicAdd(gp + 3, y3);
    }
}

// ---------------- final: divide pooled sums by counts ----------------
__global__ void k_final(float* __restrict__ out) {
    int i = blockIdx.x * blockDim.x + threadIdx.x;
    if (i < NGRAPH * DIM)
        out[i] = out[i] / fmaxf(g_gcnt[i >> 7], 1.0f);
}

// ---------------- launch ----------------
extern "C" void kernel_launch(void* const* d_in, const int* in_sizes, int n_in,
                              void* d_out, int out_size) {
    const float* x     = (const float*)d_in[0];
    const void*  ei    = d_in[1];
    const void*  batch = d_in[2];
    const float* W1    = (const float*)d_in[3];
    const float* as1   = (const float*)d_in[4];
    const float* ad1   = (const float*)d_in[5];
    const float* b1    = (const float*)d_in[6];
    const float* W2    = (const float*)d_in[7];
    const float* as2   = (const float*)d_in[8];
    const float* ad2   = (const float*)d_in[9];
    const float* b2    = (const float*)d_in[10];
    const float* gam   = (const float*)d_in[11];
    const float* bet   = (const float*)d_in[12];
    float* out = (float*)d_out;

    const int SCAN_BLOCKS = (N_NODES + 511) / 512;   // 391

    k_detect<<<1, 1>>>(ei);
    k_init<<<(N_NODES + 255) / 256, 256>>>();
    k_zero_out<<<(NGRAPH * DIM + 255) / 256, 256>>>(out);
    k_hist<<<(N_NODES + 255) / 256, 256>>>(batch);
    k_deg<<<(N_EDGES + 255) / 256, 256>>>(ei);
    k_scan1<<<SCAN_BLOCKS, 512>>>();
    k_scan2<<<1, 32>>>(SCAN_BLOCKS);
    k_scan3<<<SCAN_BLOCKS, 512>>>();
    k_scatter<<<(EE_TOT + 255) / 256, 256>>>(ei);

    // layer 1
    k_proj1<<<1, 128>>>(W1, as1, ad1);
    k_dots_x<<<(N_NODES * 32 + 255) / 256, 256>>>(x);
    k_fused1<<<N_NODES / 32, 256>>>(x, W1, b1);

    // layer 2
    k_proj2<<<1, 128>>>(W2, as2, ad2);
    k_dots_h<<<(N_NODES * 32 + 255) / 256, 256>>>();
    k_fused2<<<N_NODES / 64, 512>>>(W2, b2, gam, bet, batch, out);

    k_final<<<(NGRAPH * DIM + 255) / 256, 256>>>(out);
}

// round 8
// speedup vs baseline: 1.0842x; 1.0842x over previous
#include <cuda_runtime.h>
#include <cuda_fp16.h>

#define N_NODES 200000
#define N_EDGES 600000
#define EE_TOT  800000
#define NGRAPH  20000
#define DIM     128
#define NEG_SLOPE 0.2f
#define LN_EPS 1e-5f

// ---------------- device scratch: total ~64.9 MB ----------------
__device__ int    g_idx64;
__device__ __align__(16) __half g_hbuf[(long long)N_NODES*DIM]; // 51.2 MB, layer-1 activations
__device__ __align__(16) float  g_asrc[N_NODES*4];              // 3.2 MB, layer-1 logits
__device__ __align__(16) float  g_adst[N_NODES*4];              // 3.2 MB
__device__ float  g_asrc2[N_NODES];                             // 0.8 MB, layer-2 logits
__device__ float  g_adst2[N_NODES];                             // 0.8 MB
__device__ int    g_col[EE_TOT];                                // 3.2 MB
__device__ int    g_rowptr[N_NODES+1];
__device__ int    g_deg[N_NODES];
__device__ int    g_fill[N_NODES];
__device__ int    g_bsum[512];
__device__ float  g_gcnt[NGRAPH];
__device__ float  g_p1[4*DIM], g_q1[4*DIM];   // projected att vectors, layer 1
__device__ float  g_p2[DIM],   g_q2[DIM];     // layer 2

__device__ __forceinline__ int load_idx(const void* p, long long i) {
    if (g_idx64) return (int)((const long long*)p)[i];
    return ((const int*)p)[i];
}
__device__ __forceinline__ float lrelu(float a) { return a > 0.0f ? a : NEG_SLOPE * a; }

// ---------------- dtype sniff (one warp) ----------------
__global__ void k_detect(const void* ei) {
    const int* p = (const int*)ei;
    int lane = threadIdx.x;
    int orr = 0;
    for (int i = 1 + 2 * lane; i < 2000; i += 64) orr |= p[i];  // odd words
#pragma unroll
    for (int o = 16; o; o >>= 1) orr |= __shfl_xor_sync(0xFFFFFFFFu, orr, o);
    if (lane == 0) g_idx64 = (orr == 0) ? 1 : 0;
}

// ---------------- init (covers out, deg/fill, gcnt) ----------------
__global__ void k_init(float* out) {
    int i = blockIdx.x * blockDim.x + threadIdx.x;
    if (i < NGRAPH * DIM) out[i] = 0.0f;
    if (i < N_NODES) { g_deg[i] = 1; g_fill[i] = 0; }   // self loop
    if (i < NGRAPH)  g_gcnt[i] = 0.0f;
}

// ---------------- degree histogram + per-graph counts ----------------
__global__ void k_histdeg(const void* ei, const void* batch) {
    int e = blockIdx.x * blockDim.x + threadIdx.x;
    if (e < N_EDGES) atomicAdd(&g_deg[load_idx(ei, (long long)N_EDGES + e)], 1);
    if (e < N_NODES) atomicAdd(&g_gcnt[load_idx(batch, e)], 1.0f);
}

// ---------------- exclusive scan of g_deg -> g_rowptr ----------------
__global__ void k_scan1() {
    __shared__ int sh[512];
    int gid = blockIdx.x * 512 + threadIdx.x;
    int v = (gid < N_NODES) ? g_deg[gid] : 0;
    sh[threadIdx.x] = v;
    __syncthreads();
    for (int off = 1; off < 512; off <<= 1) {
        int t = (threadIdx.x >= off) ? sh[threadIdx.x - off] : 0;
        __syncthreads();
        sh[threadIdx.x] += t;
        __syncthreads();
    }
    if (gid < N_NODES) g_rowptr[gid] = sh[threadIdx.x] - v;
    if (threadIdx.x == 511) g_bsum[blockIdx.x] = sh[511];
}
__global__ void k_scan2(int nblocks) {
    if (threadIdx.x == 0 && blockIdx.x == 0) {
        int run = 0;
        for (int i = 0; i < nblocks; i++) { int t = g_bsum[i]; g_bsum[i] = run; run += t; }
    }
}
__global__ void k_scan3() {
    int gid = blockIdx.x * 512 + threadIdx.x;
    if (gid < N_NODES) g_rowptr[gid] += g_bsum[blockIdx.x];
    if (gid == 0) g_rowptr[N_NODES] = EE_TOT;
}
__global__ void k_scatter(const void* ei) {
    int e = blockIdx.x * blockDim.x + threadIdx.x;
    if (e >= EE_TOT) return;
    int s, d;
    if (e < N_EDGES) {
        s = load_idx(ei, e);
        d = load_idx(ei, (long long)N_EDGES + e);
    } else {
        s = d = e - N_EDGES;
    }
    int pos = g_rowptr[d] + atomicAdd(&g_fill[d], 1);
    g_col[pos] = s;
}

// ---------------- projected attention vectors (block 0: layer1, block 1: layer2)
__global__ void k_proj(const float* __restrict__ W1,
                       const float* __restrict__ as1,
                       const float* __restrict__ ad1,
                       const float* __restrict__ W2,
                       const float* __restrict__ as2,
                       const float* __restrict__ ad2) {
    int c = threadIdx.x;
    if (blockIdx.x == 0) {
#pragma unroll
        for (int hd = 0; hd < 4; hd++) {
            float sp = 0.0f, sq = 0.0f;
#pragma unroll
            for (int j = 0; j < 32; j++) {
                float wv = W1[c * 128 + hd * 32 + j];
                sp += wv * as1[hd * 32 + j];
                sq += wv * ad1[hd * 32 + j];
            }
            g_p1[hd * 128 + c] = sp;
            g_q1[hd * 128 + c] = sq;
        }
    } else {
        float sp = 0.0f, sq = 0.0f;
        for (int j = 0; j < 128; j++) {
            float wv = W2[c * 128 + j];
            sp += wv * as2[j];
            sq += wv * ad2[j];
        }
        g_p2[c] = sp;
        g_q2[c] = sq;
    }
}

// ---------------- layer-1 logits per node ----------------
__global__ void k_dots_x(const float* __restrict__ x) {
    int n    = (blockIdx.x * blockDim.x + threadIdx.x) >> 5;
    int lane = threadIdx.x & 31;
    if (n >= N_NODES) return;
    float4 xv = *(const float4*)&x[(long long)n * 128 + lane * 4];
    float s[4], d[4];
#pragma unroll
    for (int hd = 0; hd < 4; hd++) {
        float4 pv = *(const float4*)&g_p1[hd * 128 + lane * 4];
        float4 qv = *(const float4*)&g_q1[hd * 128 + lane * 4];
        s[hd] = xv.x * pv.x + xv.y * pv.y + xv.z * pv.z + xv.w * pv.w;
        d[hd] = xv.x * qv.x + xv.y * qv.y + xv.z * qv.z + xv.w * qv.w;
    }
#pragma unroll
    for (int hd = 0; hd < 4; hd++)
#pragma unroll
        for (int o = 16; o; o >>= 1) {
            s[hd] += __shfl_xor_sync(0xFFFFFFFFu, s[hd], o);
            d[hd] += __shfl_xor_sync(0xFFFFFFFFu, d[hd], o);
        }
    if (lane == 0) {
        *(float4*)&g_asrc[n * 4] = make_float4(s[0], s[1], s[2], s[3]);
        *(float4*)&g_adst[n * 4] = make_float4(d[0], d[1], d[2], d[3]);
    }
}

// ---------------- layer 1 fused: aggregate(x) + per-head GEMM + bias + relu
//                  + layer-2 logits (h1·p2, h1·q2) written to g_asrc2/g_adst2
// 256 threads, 32 dst rows/block.
__global__ __launch_bounds__(256) void k_fused1(const float* __restrict__ x,
                                                const float* __restrict__ W1,
                                                const float* __restrict__ b1) {
    __shared__ __half Ush[32 * 512];
    __shared__ float  Wsh[128 * 32];
    int t = threadIdx.x;
    int w = t >> 5, lane = t & 31;
    long long rowBase = (long long)blockIdx.x * 32;

    // Phase A: per-head softmax aggregation in input space
    for (int rr = 0; rr < 4; rr++) {
        int row = w * 4 + rr;
        long long n = rowBase + row;
        int beg = g_rowptr[n], end = g_rowptr[n + 1];
        float4 ad = *(const float4*)&g_adst[n * 4];
        float m0 = -1e30f, m1 = -1e30f, m2 = -1e30f, m3 = -1e30f;
        for (int e = beg; e < end; e++) {
            int s = g_col[e];
            float4 as = *(const float4*)&g_asrc[s * 4];
            m0 = fmaxf(m0, lrelu(as.x + ad.x));
            m1 = fmaxf(m1, lrelu(as.y + ad.y));
            m2 = fmaxf(m2, lrelu(as.z + ad.z));
            m3 = fmaxf(m3, lrelu(as.w + ad.w));
        }
        float acc[4][4];
#pragma unroll
        for (int a = 0; a < 4; a++)
#pragma unroll
            for (int b = 0; b < 4; b++) acc[a][b] = 0.0f;
        float den0 = 0, den1 = 0, den2 = 0, den3 = 0;
        for (int e = beg; e < end; e++) {
            int s = g_col[e];
            float4 as = *(const float4*)&g_asrc[s * 4];
            float w0 = __expf(lrelu(as.x + ad.x) - m0); den0 += w0;
            float w1 = __expf(lrelu(as.y + ad.y) - m1); den1 += w1;
            float w2 = __expf(lrelu(as.z + ad.z) - m2); den2 += w2;
            float w3 = __expf(lrelu(as.w + ad.w) - m3); den3 += w3;
            float4 xv = *(const float4*)&x[(long long)s * 128 + lane * 4];
            acc[0][0] += w0 * xv.x; acc[0][1] += w0 * xv.y; acc[0][2] += w0 * xv.z; acc[0][3] += w0 * xv.w;
            acc[1][0] += w1 * xv.x; acc[1][1] += w1 * xv.y; acc[1][2] += w1 * xv.z; acc[1][3] += w1 * xv.w;
            acc[2][0] += w2 * xv.x; acc[2][1] += w2 * xv.y; acc[2][2] += w2 * xv.z; acc[2][3] += w2 * xv.w;
            acc[3][0] += w3 * xv.x; acc[3][1] += w3 * xv.y; acc[3][2] += w3 * xv.z; acc[3][3] += w3 * xv.w;
        }
        float den[4] = {den0, den1, den2, den3};
#pragma unroll
        for (int hd = 0; hd < 4; hd++) {
            float inv = 1.0f / den[hd];
            __half2* dst = (__half2*)&Ush[row * 512 + hd * 128 + lane * 4];
            dst[0] = __floats2half2_rn(acc[hd][0] * inv, acc[hd][1] * inv);
            dst[1] = __floats2half2_rn(acc[hd][2] * inv, acc[hd][3] * inv);
        }
    }

    // Phase B: per-head GEMM u_hd[32,128] @ W1[:, hd*32:+32]; accumulate
    // layer-2 logit partials on the fly.
    int row = t >> 3;   // 0..31
    int tx8 = t & 7;    // col group of 4 within 32
    float sdot = 0.0f, ddot = 0.0f;
    for (int hd = 0; hd < 4; hd++) {
        __syncthreads();   // Phase A done / previous head's Wsh reads done
#pragma unroll
        for (int p = 0; p < 4; p++) {
            int idx = t + p * 256;        // 0..1023
            int r   = idx >> 3;           // 0..127
            int c4  = idx & 7;
            *(float4*)&Wsh[r * 32 + c4 * 4] = *(const float4*)&W1[r * 128 + hd * 32 + c4 * 4];
        }
        __syncthreads();
        float a0 = 0, a1 = 0, a2 = 0, a3 = 0;
        const __half2* u2 = (const __half2*)&Ush[row * 512 + hd * 128];
#pragma unroll 16
        for (int k2 = 0; k2 < 64; k2++) {
            float2 av = __half22float2(u2[k2]);
            const float* w0 = &Wsh[(2 * k2) * 32 + tx8 * 4];
            const float* w1 = &Wsh[(2 * k2 + 1) * 32 + tx8 * 4];
            a0 += av.x * w0[0] + av.y * w1[0];
            a1 += av.x * w0[1] + av.y * w1[1];
            a2 += av.x * w0[2] + av.y * w1[2];
            a3 += av.x * w0[3] + av.y * w1[3];
        }
        int c = hd * 32 + tx8 * 4;
        long long n = rowBase + row;
        float v0 = a0 + b1[c];     v0 = v0 > 0 ? v0 : 0.0f;
        float v1 = a1 + b1[c + 1]; v1 = v1 > 0 ? v1 : 0.0f;
        float v2 = a2 + b1[c + 2]; v2 = v2 > 0 ? v2 : 0.0f;
        float v3 = a3 + b1[c + 3]; v3 = v3 > 0 ? v3 : 0.0f;
        sdot += v0 * g_p2[c] + v1 * g_p2[c + 1] + v2 * g_p2[c + 2] + v3 * g_p2[c + 3];
        ddot += v0 * g_q2[c] + v1 * g_q2[c + 1] + v2 * g_q2[c + 2] + v3 * g_q2[c + 3];
        __half2* dst = (__half2*)&g_hbuf[n * 128 + c];
        dst[0] = __floats2half2_rn(v0, v1);
        dst[1] = __floats2half2_rn(v2, v3);
    }
    // reduce layer-2 logits across the 8 threads of this row (same warp)
#pragma unroll
    for (int o = 4; o; o >>= 1) {
        sdot += __shfl_down_sync(0xFFFFFFFFu, sdot, o, 8);
        ddot += __shfl_down_sync(0xFFFFFFFFu, ddot, o, 8);
    }
    if (tx8 == 0) {
        long long n = rowBase + row;
        g_asrc2[n] = sdot;
        g_adst2[n] = ddot;
    }
}

// ---------------- layer 2 fused: aggregate(h1) + GEMM + bias + LN + pool -----
// 512 threads, 64 dst rows/block.
__global__ __launch_bounds__(512) void k_fused2(const float* __restrict__ W2,
                                                const float* __restrict__ b2,
                                                const float* __restrict__ gamma,
                                                const float* __restrict__ beta,
                                                const void* batch,
                                                float* __restrict__ out) {
    __shared__ float Ash[64 * 128];
    __shared__ float Wsh[32 * 128];
    int t = threadIdx.x;
    int w = t >> 5, lane = t & 31;
    long long rowBase = (long long)blockIdx.x * 64;

    // Phase A: softmax aggregation of h1 (single head)
    for (int rr = 0; rr < 4; rr++) {
        int row = w * 4 + rr;
        long long n = rowBase + row;
        int beg = g_rowptr[n], end = g_rowptr[n + 1];
        float ad = g_adst2[n];
        float m = -1e30f;
        for (int e = beg; e < end; e++)
            m = fmaxf(m, lrelu(g_asrc2[g_col[e]] + ad));
        float a0 = 0, a1 = 0, a2 = 0, a3 = 0, den = 0;
        for (int e = beg; e < end; e++) {
            int s = g_col[e];
            float wgt = __expf(lrelu(g_asrc2[s] + ad) - m);
            den += wgt;
            const __half2* hp = (const __half2*)&g_hbuf[(long long)s * 128 + lane * 4];
            float2 p0 = __half22float2(hp[0]);
            float2 p1 = __half22float2(hp[1]);
            a0 += wgt * p0.x; a1 += wgt * p0.y; a2 += wgt * p1.x; a3 += wgt * p1.y;
        }
        float inv = 1.0f / den;
        *(float4*)&Ash[row * 128 + lane * 4] = make_float4(a0 * inv, a1 * inv, a2 * inv, a3 * inv);
    }
    __syncthreads();

    // Phase B: GEMM 64x128 @ 128x128 (4x4 register blocking)
    int tx = t & 31, ty = t >> 5;
    float acc[4][4];
#pragma unroll
    for (int i = 0; i < 4; i++)
#pragma unroll
        for (int j = 0; j < 4; j++) acc[i][j] = 0.0f;
    for (int kt = 0; kt < 128; kt += 32) {
#pragma unroll
        for (int p = 0; p < 2; p++) {
            int idx = t + p * 512;
            int kk  = idx >> 5;
            int c4  = idx & 31;
            *(float4*)&Wsh[kk * 128 + c4 * 4] = *(const float4*)&W2[(kt + kk) * 128 + c4 * 4];
        }
        __syncthreads();
#pragma unroll
        for (int k = 0; k < 32; k++) {
            float4 wv = *(const float4*)&Wsh[k * 128 + tx * 4];
#pragma unroll
            for (int i = 0; i < 4; i++) {
                float a = Ash[(ty * 4 + i) * 128 + kt + k];
                acc[i][0] += a * wv.x;
                acc[i][1] += a * wv.y;
                acc[i][2] += a * wv.z;
                acc[i][3] += a * wv.w;
            }
        }
        __syncthreads();
    }

    // epilogue: bias + LN (warp owns rows fully) + pooled atomics with
    // run-detection over consecutive rows sharing a graph id (batch is sorted)
    float4 b2v = *(const float4*)&b2[tx * 4];
    float4 gv  = *(const float4*)&gamma[tx * 4];
    float4 bev = *(const float4*)&beta[tx * 4];
    int gprev = -1;
    float s0 = 0, s1 = 0, s2 = 0, s3 = 0;
#pragma unroll
    for (int i = 0; i < 4; i++) {
        long long n = rowBase + ty * 4 + i;
        float v0 = acc[i][0] + b2v.x;
        float v1 = acc[i][1] + b2v.y;
        float v2 = acc[i][2] + b2v.z;
        float v3 = acc[i][3] + b2v.w;
        float s = v0 + v1 + v2 + v3;
#pragma unroll
        for (int o = 16; o; o >>= 1) s += __shfl_xor_sync(0xFFFFFFFFu, s, o);
        float mu = s * (1.0f / 128.0f);
        float c0 = v0 - mu, c1 = v1 - mu, c2 = v2 - mu, c3 = v3 - mu;
        float sq = c0 * c0 + c1 * c1 + c2 * c2 + c3 * c3;
#pragma unroll
        for (int o = 16; o; o >>= 1) sq += __shfl_xor_sync(0xFFFFFFFFu, sq, o);
        float rstd = rsqrtf(sq * (1.0f / 128.0f) + LN_EPS);
        float y0 = c0 * rstd * gv.x + bev.x;
        float y1 = c1 * rstd * gv.y + bev.y;
        float y2 = c2 * rstd * gv.z + bev.z;
        float y3 = c3 * rstd * gv.w + bev.w;
        int g = load_idx(batch, n);
        if (g != gprev) {
            if (gprev >= 0) {
                float* gp = &out[(long long)gprev * 128 + tx * 4];
                atomicAdd(gp + 0, s0);
                atomicAdd(gp + 1, s1);
                atomicAdd(gp + 2, s2);
                atomicAdd(gp + 3, s3);
            }
            gprev = g; s0 = y0; s1 = y1; s2 = y2; s3 = y3;
        } else {
            s0 += y0; s1 += y1; s2 += y2; s3 += y3;
        }
    }
    {
        float* gp = &out[(long long)gprev * 128 + tx * 4];
        atomicAdd(gp + 0, s0);
        atomicAdd(gp + 1, s1);
        atomicAdd(gp + 2, s2);
        atomicAdd(gp + 3, s3);
    }
}

// ---------------- final: divide pooled sums by counts ----------------
__global__ void k_final(float* __restrict__ out) {
    int i = blockIdx.x * blockDim.x + threadIdx.x;
    if (i < NGRAPH * DIM)
        out[i] = out[i] / fmaxf(g_gcnt[i >> 7], 1.0f);
}

// ---------------- launch ----------------
extern "C" void kernel_launch(void* const* d_in, const int* in_sizes, int n_in,
                              void* d_out, int out_size) {
    const float* x     = (const float*)d_in[0];
    const void*  ei    = d_in[1];
    const void*  batch = d_in[2];
    const float* W1    = (const float*)d_in[3];
    const float* as1   = (const float*)d_in[4];
    const float* ad1   = (const float*)d_in[5];
    const float* b1    = (const float*)d_in[6];
    const float* W2    = (const float*)d_in[7];
    const float* as2   = (const float*)d_in[8];
    const float* ad2   = (const float*)d_in[9];
    const float* b2    = (const float*)d_in[10];
    const float* gam   = (const float*)d_in[11];
    const float* bet   = (const float*)d_in[12];
    float* out = (float*)d_out;

    const int SCAN_BLOCKS = (N_NODES + 511) / 512;   // 391

    k_detect<<<1, 32>>>(ei);
    k_init<<<(NGRAPH * DIM + 255) / 256, 256>>>(out);
    k_histdeg<<<(N_EDGES + 255) / 256, 256>>>(ei, batch);
    k_scan1<<<SCAN_BLOCKS, 512>>>();
    k_scan2<<<1, 32>>>(SCAN_BLOCKS);
    k_scan3<<<SCAN_BLOCKS, 512>>>();
    k_scatter<<<(EE_TOT + 255) / 256, 256>>>(ei);
    k_proj<<<2, 128>>>(W1, as1, ad1, W2, as2, ad2);

    // layer 1 (+ layer-2 logits fused into Phase B)
    k_dots_x<<<(N_NODES * 32 + 255) / 256, 256>>>(x);
    k_fused1<<<N_NODES / 32, 256>>>(x, W1, b1);

    // layer 2
    k_fused2<<<N_NODES / 64, 512>>>(W2, b2, gam, bet, batch, out);

    k_final<<<(NGRAPH * DIM + 255) / 256, 256>>>(out);
}